// round 12
// baseline (speedup 1.0000x reference)
#include <cuda_runtime.h>
#include <cuda_bf16.h>

// Retrace loss — persistent CTAs + vectorized (LDG.128) misalignment-aware loads.
// row*1025 ≡ bid (mod 4) and grid stride 592 ≡ 0 (mod 4)  =>  alignment residue
// A = bid&3 is constant per CTA -> template<A> specialization, compile-time realign.
// Each lane loads one aligned float4 chunk per array; missing head words come via
// shfl_down(1); lane 31 does one predicated extra chunk load (clamped at buffer end,
// feeding only the discarded j==1023 identity slot).
// Pipeline: issue raw chunk loads for next row early; realign (shfls) at consume.
// Scan: serial compose 4 -> one warp suffix scan -> redundant cross-warp combine
// with double-buffered totals and a single __syncthreads per row.

#define S_STRIDE 1025
#define T_LEN    1024
#define NROWS    4096
#define GAMMA_F  0.99f
#define EPS_F    1e-10f
#define NTHREADS 256
#define GRID     592
#define NWC      1049600   // (4096*1025)/4 aligned float4 chunks per array

__device__ double   g_part[GRID];
__device__ unsigned g_cnt = 0;   // wraps at GRID-1 -> deterministic across replays

struct Aff { float a, b; };

__device__ __forceinline__ Aff comp(Aff f, Aff g) {
    Aff r;
    r.a = fmaf(f.b, g.a, f.a);
    r.b = f.b * g.b;
    return r;
}

// Raw gather state: one aligned chunk + (lane31-only) head of next chunk.
template<int D>
struct RawG { float4 c; float nx, ny, nz; };

// Issue loads only (no shfl -> no stall at issue time).
// w0 = first needed word; w0 - D is 16B aligned by construction.
template<int D>
__device__ __forceinline__ void gissue(RawG<D>& g, const float* __restrict__ ptr,
                                       int w0, int lane)
{
    const int cb4 = (w0 - D) >> 2;
    g.c = __ldg(reinterpret_cast<const float4*>(ptr) + (cb4 + lane));
    if (D > 0) {
        if (lane == 31) {
            const int ce = min(cb4 + 32, NWC - 1);   // clamp: only ever OOB feeding j>=1023
            const float4 e = __ldg(reinterpret_cast<const float4*>(ptr) + ce);
            g.nx = e.x; g.ny = e.y; g.nz = e.z;
        }
    }
}

// Realign at consume time: words w0+4*lane .. +3.
template<int D>
__device__ __forceinline__ float4 gfinish(const RawG<D>& g, int lane) {
    if (D == 0) return g.c;
    float nx = __shfl_down_sync(0xffffffffu, g.c.x, 1);
    float ny = 0.0f, nz = 0.0f;
    if (D >= 2) ny = __shfl_down_sync(0xffffffffu, g.c.y, 1);
    if (D >= 3) nz = __shfl_down_sync(0xffffffffu, g.c.z, 1);
    if (lane == 31) { nx = g.nx; if (D >= 2) ny = g.ny; if (D >= 3) nz = g.nz; }
    float4 o;
    if (D == 1)      { o.x = g.c.y; o.y = g.c.z; o.z = g.c.w; o.w = nx; }
    else if (D == 2) { o.x = g.c.z; o.y = g.c.w; o.z = nx;    o.w = ny; }
    else             { o.x = g.c.w; o.y = nx;    o.z = ny;    o.w = nz; }
    return o;
}

template<int A>
__device__ __forceinline__ double run_rows(
    const float* __restrict__ Q,  const float* __restrict__ eQ,
    const float* __restrict__ tQ, const float* __restrict__ r,
    const float* __restrict__ tp, const float* __restrict__ bp,
    float (&swA)[2][8], float (&swB)[2][8])
{
    constexpr int DR = (A + 1) & 3;   // residue of the +1-shifted array (r)
    constexpr int DE = (A + 2) & 3;   // residue of the +2-shifted arrays

    const int t = threadIdx.x;
    const int lane = t & 31;
    const int w = t >> 5;
    const int seg = w * 128;
    const int j0 = seg + 4 * lane;    // this thread's first col

    double acc = 0.0;
    RawG<DR> Prv; RawG<DE> Pev, Ptq, Ppt, Ppb;

    int row = blockIdx.x;
    {
        const int wb = row * S_STRIDE + seg;
        gissue(Prv, r,  wb + 1, lane);
        gissue(Pev, eQ, wb + 2, lane);
        gissue(Ptq, tQ, wb + 2, lane);
        gissue(Ppt, tp, wb + 2, lane);
        gissue(Ppb, bp, wb + 2, lane);
    }

    int buf = 0;
    while (row < NROWS) {
        const int next = row + GRID;
        const int wb = row * S_STRIDE + seg;

        // current row's Q loads: issued now, realigned at epilogue (scan hides latency)
        RawG<A> Pq;
        gissue(Pq, Q, wb, lane);
        const float initv = __ldg(&Q[row * S_STRIDE + T_LEN]);

        // realize prefetched map inputs
        const float4 rv = gfinish(Prv, lane);
        const float4 ev = gfinish(Pev, lane);
        const float4 tq = gfinish(Ptq, lane);
        const float4 pt = gfinish(Ppt, lane);
        const float4 pb = gfinish(Ppb, lane);

        // issue next row's raw loads; they fly during the scan below
        if (next < NROWS) {
            const int wb2 = next * S_STRIDE + seg;
            gissue(Prv, r,  wb2 + 1, lane);
            gissue(Pev, eQ, wb2 + 2, lane);
            gissue(Ptq, tQ, wb2 + 2, lane);
            gissue(Ppt, tp, wb2 + 2, lane);
            gissue(Ppb, bp, wb2 + 2, lane);
        }

        // build affine maps (identity for j==1023)
        const float PT[4] = {pt.x, pt.y, pt.z, pt.w};
        const float PB[4] = {pb.x, pb.y, pb.z, pb.w};
        const float RV[4] = {rv.x, rv.y, rv.z, rv.w};
        const float EV[4] = {ev.x, ev.y, ev.z, ev.w};
        const float TQ[4] = {tq.x, tq.y, tq.z, tq.w};
        Aff loc[4];
#pragma unroll
        for (int k = 0; k < 4; k++) {
            if (j0 + k < T_LEN - 1) {
                const float c = fminf(fmaxf(__fdividef(PT[k], PB[k]), EPS_F), 1.0f);
                loc[k].b = GAMMA_F * c;
                loc[k].a = fmaf(GAMMA_F, EV[k], RV[k]) - loc[k].b * TQ[k];
            } else {
                loc[k].a = 0.0f; loc[k].b = 1.0f;
            }
        }

        // serial suffix composition within thread
        Aff suf[4];
        suf[3] = loc[3];
#pragma unroll
        for (int k = 2; k >= 0; k--) suf[k] = comp(loc[k], suf[k + 1]);

        // one warp-level inclusive suffix scan of thread aggregates
        Aff v = suf[0];
#pragma unroll
        for (int off = 1; off < 32; off <<= 1) {
            const float oa = __shfl_down_sync(0xffffffffu, v.a, off);
            const float ob = __shfl_down_sync(0xffffffffu, v.b, off);
            if (lane + off < 32) { Aff g; g.a = oa; g.b = ob; v = comp(v, g); }
        }

        // in-warp EXCLUSIVE suffix (threads lane+1..31)
        const float ea = __shfl_down_sync(0xffffffffu, v.a, 1);
        const float eb = __shfl_down_sync(0xffffffffu, v.b, 1);
        Aff inwexcl;
        if (lane == 31) { inwexcl.a = 0.0f; inwexcl.b = 1.0f; }
        else            { inwexcl.a = ea;   inwexcl.b = eb;   }

        // cross-warp: publish totals (double-buffered), ONE barrier,
        // then each thread redundantly composes its warp's exclusive suffix
        if (lane == 0) { swA[buf][w] = v.a; swB[buf][w] = v.b; }
        __syncthreads();
        Aff W; W.a = 0.0f; W.b = 1.0f;
        for (int ww = 7; ww > w; ww--) {
            Aff tot; tot.a = swA[buf][ww]; tot.b = swB[buf][ww];
            W = comp(tot, W);
        }
        const Aff S = comp(inwexcl, W);

        // epilogue: realign Q, apply composed maps, accumulate squared error
        const float4 q4 = gfinish(Pq, lane);
        const float QV[4] = {q4.x, q4.y, q4.z, q4.w};
        float fsum = 0.0f;
#pragma unroll
        for (int k = 0; k < 4; k++) {
            const Aff m = comp(suf[k], S);
            const float y = fmaf(m.b, initv, m.a);
            const float d = QV[k] - y;
            fsum = fmaf(d, d, fsum);
        }
        acc += (double)fsum;

        buf ^= 1;
        row = next;
    }
    return acc;
}

__global__ void __launch_bounds__(NTHREADS, 4)
retrace_kernel(const float* __restrict__ Q,
               const float* __restrict__ eQ,
               const float* __restrict__ tQ,
               const float* __restrict__ r,
               const float* __restrict__ tp,
               const float* __restrict__ bp,
               float* __restrict__ out)
{
    __shared__ float swA[2][8], swB[2][8];
    __shared__ double ssum[8];
    __shared__ bool s_last;

    double acc;
    switch (blockIdx.x & 3) {
        case 0:  acc = run_rows<0>(Q, eQ, tQ, r, tp, bp, swA, swB); break;
        case 1:  acc = run_rows<1>(Q, eQ, tQ, r, tp, bp, swA, swB); break;
        case 2:  acc = run_rows<2>(Q, eQ, tQ, r, tp, bp, swA, swB); break;
        default: acc = run_rows<3>(Q, eQ, tQ, r, tp, bp, swA, swB); break;
    }

    const int t = threadIdx.x;
    const int lane = t & 31;
    const int w = t >> 5;

    // block-reduce per-thread doubles, one arrival per CTA
#pragma unroll
    for (int off = 16; off > 0; off >>= 1)
        acc += __shfl_down_sync(0xffffffffu, acc, off);
    if (lane == 0) ssum[w] = acc;
    __syncthreads();

    if (t == 0) {
        double x = 0.0;
#pragma unroll
        for (int i = 0; i < 8; i++) x += ssum[i];
        __stcg(&g_part[blockIdx.x], x);
        __threadfence();
        const unsigned old = atomicInc(&g_cnt, GRID - 1);  // wraps after GRID arrivals
        s_last = (old == GRID - 1);
    }
    __syncthreads();

    // very last CTA reduces all partials and writes output
    if (s_last) {
        double x = 0.0;
        for (int i = t; i < GRID; i += NTHREADS)
            x += __ldcg(&g_part[i]);
#pragma unroll
        for (int off = 16; off > 0; off >>= 1)
            x += __shfl_down_sync(0xffffffffu, x, off);
        __shared__ double fs2[8];
        if (lane == 0) fs2[w] = x;
        __syncthreads();
        if (t == 0) {
            double tot = 0.0;
#pragma unroll
            for (int i = 0; i < 8; i++) tot += fs2[i];
            out[0] = (float)(tot / (double)((long long)NROWS * T_LEN));
        }
    }
}

extern "C" void kernel_launch(void* const* d_in, const int* in_sizes, int n_in,
                              void* d_out, int out_size)
{
    const float* Q   = (const float*)d_in[0];
    const float* eQ  = (const float*)d_in[1];
    const float* tQ  = (const float*)d_in[2];
    const float* r   = (const float*)d_in[3];
    const float* tp  = (const float*)d_in[4];
    const float* bp  = (const float*)d_in[5];
    float* out = (float*)d_out;

    retrace_kernel<<<GRID, NTHREADS>>>(Q, eQ, tQ, r, tp, bp, out);
}

// round 13
// speedup vs baseline: 1.2710x; 1.2710x over previous
#include <cuda_runtime.h>
#include <cuda_bf16.h>

// Retrace loss — persistent CTAs + float2 (LDG.64) misalignment-aware loads.
// row*1025 ≡ bid (mod 2), grid stride 592 even  =>  parity A2 = bid&1 constant
// per CTA. Arrays with even shift (Q,eQ,tQ,tp,bp) have residue A2; r (shift+1)
// has residue A2^1 -> exactly ONE array class is misaligned per CTA.
// Misaligned realign = 1 shfl_down + lane31 scalar word (all lane31 extras in
// one divergent block). No smem transpose: gather directly yields cols 4t..4t+3.
// Scan: serial compose 4 -> one warp suffix scan -> redundant cross-warp combine
// (double-buffered totals, single __syncthreads per row).
// Affine composition: (A1,B1) o (A2,B2) = (A1 + B1*A2, B1*B2).

#define S_STRIDE 1025
#define T_LEN    1024
#define NROWS    4096
#define GAMMA_F  0.99f
#define EPS_F    1e-10f
#define NTHREADS 256
#define GRID     592
#define NTOT     4198400   // 4096*1025 words per array

__device__ double   g_part[GRID];
__device__ unsigned g_cnt = 0;   // wraps at GRID-1 -> deterministic across replays

struct Aff { float a, b; };

__device__ __forceinline__ Aff comp(Aff f, Aff g) {
    Aff r;
    r.a = fmaf(f.b, g.a, f.a);
    r.b = f.b * g.b;
    return r;
}

// float2 gather state: words w0+4*lane .. +3 live in chunks (w0-D)/2 + 2*lane, +1.
template<int D>
struct G2 { float2 e0, e1; float ext; };

template<int D>
__device__ __forceinline__ void g2issue(G2<D>& g, const float* __restrict__ ptr,
                                        int w0, int lane)
{
    const int cb = (w0 - D) >> 1;                 // (w0-D) even by construction
    const float2* p2 = reinterpret_cast<const float2*>(ptr);
    g.e0 = __ldg(p2 + (cb + 2 * lane));
    g.e1 = __ldg(p2 + (cb + 2 * lane + 1));
}

template<int D>
__device__ __forceinline__ float4 g2finish(const G2<D>& g, int lane) {
    float4 o;
    if (D == 0) {
        o.x = g.e0.x; o.y = g.e0.y; o.z = g.e1.x; o.w = g.e1.y;
    } else {
        // e0 = {w0-1+4l, w0+4l}, e1 = {w0+1+4l, w0+2+4l}; o3 from lane+1's e0.x
        float o3 = __shfl_down_sync(0xffffffffu, g.e0.x, 1);
        if (lane == 31) o3 = g.ext;
        o.x = g.e0.y; o.y = g.e1.x; o.z = g.e1.y; o.w = o3;
    }
    return o;
}

template<int A2>
__device__ __forceinline__ double run_rows(
    const float* __restrict__ Q,  const float* __restrict__ eQ,
    const float* __restrict__ tQ, const float* __restrict__ r,
    const float* __restrict__ tp, const float* __restrict__ bp,
    float (&swA)[2][8], float (&swB)[2][8])
{
    constexpr int DQ = A2;       // residue of Q and the +2-shifted arrays
    constexpr int DR = A2 ^ 1;   // residue of r (+1 shift)

    const int t = threadIdx.x;
    const int lane = t & 31;
    const int w = t >> 5;
    const int seg = w * 128;
    const int j0 = seg + 4 * lane;     // this thread's first col

    double acc = 0.0;
    G2<DR> Pr; G2<DQ> Pe, Pt, Pp, Pb;

    int row = blockIdx.x;
    {
        const int wb = row * S_STRIDE + seg;
        g2issue(Pr, r,  wb + 1, lane);
        g2issue(Pe, eQ, wb + 2, lane);
        g2issue(Pt, tQ, wb + 2, lane);
        g2issue(Pp, tp, wb + 2, lane);
        g2issue(Pb, bp, wb + 2, lane);
        if (lane == 31) {   // single divergent block for all lane-31 tail words
            if (DR == 1) Pr.ext = __ldg(&r[wb + 128]);                 // always in-bounds
            if (DQ == 1) {
                const int ie = min(wb + 129, NTOT - 1);                // clamp: feeds j==1023 only
                Pe.ext = __ldg(&eQ[ie]);
                Pt.ext = __ldg(&tQ[ie]);
                Pp.ext = __ldg(&tp[ie]);
                Pb.ext = __ldg(&bp[ie]);
            }
        }
    }

    int buf = 0;
    while (row < NROWS) {
        const int next = row + GRID;
        const int wb = row * S_STRIDE + seg;

        // current row's Q gather: issued now, realigned at epilogue (scan hides latency)
        G2<DQ> Pq;
        g2issue(Pq, Q, wb, lane);
        if (DQ == 1) { if (lane == 31) Pq.ext = __ldg(&Q[wb + 127]); }  // in-bounds
        const float initv = __ldg(&Q[row * S_STRIDE + T_LEN]);

        // realize prefetched map inputs (<=1 shfl per array class)
        const float4 rv = g2finish(Pr, lane);
        const float4 ev = g2finish(Pe, lane);
        const float4 tq = g2finish(Pt, lane);
        const float4 pt = g2finish(Pp, lane);
        const float4 pb = g2finish(Pb, lane);

        // issue next row's raw loads; they fly during the scan below
        if (next < NROWS) {
            const int wb2 = next * S_STRIDE + seg;
            g2issue(Pr, r,  wb2 + 1, lane);
            g2issue(Pe, eQ, wb2 + 2, lane);
            g2issue(Pt, tQ, wb2 + 2, lane);
            g2issue(Pp, tp, wb2 + 2, lane);
            g2issue(Pb, bp, wb2 + 2, lane);
            if (lane == 31) {
                if (DR == 1) Pr.ext = __ldg(&r[wb2 + 128]);
                if (DQ == 1) {
                    const int ie = min(wb2 + 129, NTOT - 1);
                    Pe.ext = __ldg(&eQ[ie]);
                    Pt.ext = __ldg(&tQ[ie]);
                    Pp.ext = __ldg(&tp[ie]);
                    Pb.ext = __ldg(&bp[ie]);
                }
            }
        }

        // build affine maps (identity for j==1023)
        const float PT[4] = {pt.x, pt.y, pt.z, pt.w};
        const float PB[4] = {pb.x, pb.y, pb.z, pb.w};
        const float RV[4] = {rv.x, rv.y, rv.z, rv.w};
        const float EV[4] = {ev.x, ev.y, ev.z, ev.w};
        const float TQ[4] = {tq.x, tq.y, tq.z, tq.w};
        Aff loc[4];
#pragma unroll
        for (int k = 0; k < 4; k++) {
            if (j0 + k < T_LEN - 1) {
                const float c = fminf(fmaxf(__fdividef(PT[k], PB[k]), EPS_F), 1.0f);
                loc[k].b = GAMMA_F * c;
                loc[k].a = fmaf(GAMMA_F, EV[k], RV[k]) - loc[k].b * TQ[k];
            } else {
                loc[k].a = 0.0f; loc[k].b = 1.0f;
            }
        }

        // serial suffix composition within thread
        Aff suf[4];
        suf[3] = loc[3];
#pragma unroll
        for (int k = 2; k >= 0; k--) suf[k] = comp(loc[k], suf[k + 1]);

        // one warp-level inclusive suffix scan of thread aggregates
        Aff v = suf[0];
#pragma unroll
        for (int off = 1; off < 32; off <<= 1) {
            const float oa = __shfl_down_sync(0xffffffffu, v.a, off);
            const float ob = __shfl_down_sync(0xffffffffu, v.b, off);
            if (lane + off < 32) { Aff g; g.a = oa; g.b = ob; v = comp(v, g); }
        }

        // in-warp EXCLUSIVE suffix (threads lane+1..31)
        const float ea = __shfl_down_sync(0xffffffffu, v.a, 1);
        const float eb = __shfl_down_sync(0xffffffffu, v.b, 1);
        Aff inwexcl;
        if (lane == 31) { inwexcl.a = 0.0f; inwexcl.b = 1.0f; }
        else            { inwexcl.a = ea;   inwexcl.b = eb;   }

        // cross-warp: publish totals (double-buffered), ONE barrier,
        // then each thread redundantly composes its warp's exclusive suffix
        if (lane == 0) { swA[buf][w] = v.a; swB[buf][w] = v.b; }
        __syncthreads();
        Aff W; W.a = 0.0f; W.b = 1.0f;
        for (int ww = 7; ww > w; ww--) {
            Aff tot; tot.a = swA[buf][ww]; tot.b = swB[buf][ww];
            W = comp(tot, W);
        }
        const Aff S = comp(inwexcl, W);

        // epilogue: realign Q, apply composed maps, accumulate squared error
        const float4 q4 = g2finish(Pq, lane);
        const float QV[4] = {q4.x, q4.y, q4.z, q4.w};
        float fsum = 0.0f;
#pragma unroll
        for (int k = 0; k < 4; k++) {
            const Aff m = comp(suf[k], S);
            const float y = fmaf(m.b, initv, m.a);
            const float d = QV[k] - y;
            fsum = fmaf(d, d, fsum);
        }
        acc += (double)fsum;

        buf ^= 1;
        row = next;
    }
    return acc;
}

__global__ void __launch_bounds__(NTHREADS, 4)
retrace_kernel(const float* __restrict__ Q,
               const float* __restrict__ eQ,
               const float* __restrict__ tQ,
               const float* __restrict__ r,
               const float* __restrict__ tp,
               const float* __restrict__ bp,
               float* __restrict__ out)
{
    __shared__ float swA[2][8], swB[2][8];
    __shared__ double ssum[8];
    __shared__ bool s_last;

    double acc;
    if (blockIdx.x & 1) acc = run_rows<1>(Q, eQ, tQ, r, tp, bp, swA, swB);
    else                acc = run_rows<0>(Q, eQ, tQ, r, tp, bp, swA, swB);

    const int t = threadIdx.x;
    const int lane = t & 31;
    const int w = t >> 5;

    // block-reduce per-thread doubles, one arrival per CTA
#pragma unroll
    for (int off = 16; off > 0; off >>= 1)
        acc += __shfl_down_sync(0xffffffffu, acc, off);
    if (lane == 0) ssum[w] = acc;
    __syncthreads();

    if (t == 0) {
        double x = 0.0;
#pragma unroll
        for (int i = 0; i < 8; i++) x += ssum[i];
        __stcg(&g_part[blockIdx.x], x);
        __threadfence();
        const unsigned old = atomicInc(&g_cnt, GRID - 1);  // wraps after GRID arrivals
        s_last = (old == GRID - 1);
    }
    __syncthreads();

    // very last CTA reduces all partials and writes output
    if (s_last) {
        double x = 0.0;
        for (int i = t; i < GRID; i += NTHREADS)
            x += __ldcg(&g_part[i]);
#pragma unroll
        for (int off = 16; off > 0; off >>= 1)
            x += __shfl_down_sync(0xffffffffu, x, off);
        __shared__ double fs2[8];
        if (lane == 0) fs2[w] = x;
        __syncthreads();
        if (t == 0) {
            double tot = 0.0;
#pragma unroll
            for (int i = 0; i < 8; i++) tot += fs2[i];
            out[0] = (float)(tot / (double)((long long)NROWS * T_LEN));
        }
    }
}

extern "C" void kernel_launch(void* const* d_in, const int* in_sizes, int n_in,
                              void* d_out, int out_size)
{
    const float* Q   = (const float*)d_in[0];
    const float* eQ  = (const float*)d_in[1];
    const float* tQ  = (const float*)d_in[2];
    const float* r   = (const float*)d_in[3];
    const float* tp  = (const float*)d_in[4];
    const float* bp  = (const float*)d_in[5];
    float* out = (float*)d_out;

    retrace_kernel<<<GRID, NTHREADS>>>(Q, eQ, tQ, r, tp, bp, out);
}